// round 6
// baseline (speedup 1.0000x reference)
#include <cuda_runtime.h>
#include <cuda_fp16.h>
#include <cstdint>

#define B 16
#define C 256
#define O_CH 256
#define H 128
#define W 128
#define G 32
#define CG 8
#define OG 8
#define HW (H*W)

#define RSTRIP 16
#define TROWS (RSTRIP+2)   // 18 staged rows
#define TC 132             // padded cols: 0..129 used
#define NTASK (TROWS*16)   // 288 staging tasks (8 px each)

__device__ float d_mean[B*C];
__device__ float d_inv[B*C];
__device__ float d_comb[B*O_CH*CG*9];   // norm-folded weights W' = W*inv
__device__ float d_bias2[B*O_CH];       // bias' = bias - sum W'*mean

__device__ __forceinline__ uint32_t pkh2(float a, float b) {
    __half2 h = __floats2half2_rn(a, b);
    return *reinterpret_cast<uint32_t*>(&h);
}
__device__ __forceinline__ float2 uph2(uint32_t u) {
    __half2 h = *reinterpret_cast<__half2*>(&u);
    return __half22float2(h);
}
__device__ __forceinline__ uint32_t smem_u32(const void* p) {
    uint32_t a;
    asm("{ .reg .u64 t; cvta.to.shared.u64 t, %1; cvt.u32.u64 %0, t; }" : "=r"(a) : "l"(p));
    return a;
}
// swizzle on 16B units: keeps STS.128 (stride-8) and ldmatrix rows conflict-free
__device__ __forceinline__ uint32_t SW(uint32_t a16) { return a16 ^ ((a16 >> 3) & 7u); }

__device__ __forceinline__ void sts128(uint32_t addr, uint32_t a, uint32_t b, uint32_t c, uint32_t d) {
    asm volatile("st.shared.v4.b32 [%0], {%1,%2,%3,%4};" :: "r"(addr), "r"(a), "r"(b), "r"(c), "r"(d) : "memory");
}

// ---------------------------------------------------------------------------
// Kernel 1: per-(b,c) instance-norm stats.
// ---------------------------------------------------------------------------
__global__ __launch_bounds__(256) void stats_kernel(const float* __restrict__ x) {
    int idx = blockIdx.x;
    const float4* p = (const float4*)(x + (size_t)idx * HW);
    float s0 = 0.f, s1 = 0.f, q0 = 0.f, q1 = 0.f;
    #pragma unroll 4
    for (int i = threadIdx.x; i < HW/8; i += 256) {
        float4 a = p[i];
        float4 b = p[i + HW/8];
        s0 += a.x + a.y + a.z + a.w;
        q0 += a.x*a.x + a.y*a.y + a.z*a.z + a.w*a.w;
        s1 += b.x + b.y + b.z + b.w;
        q1 += b.x*b.x + b.y*b.y + b.z*b.z + b.w*b.w;
    }
    float s = s0 + s1, ss = q0 + q1;
    #pragma unroll
    for (int o = 16; o > 0; o >>= 1) {
        s  += __shfl_down_sync(0xffffffffu, s,  o);
        ss += __shfl_down_sync(0xffffffffu, ss, o);
    }
    __shared__ float as[8], bs[8];
    int lane = threadIdx.x & 31, wid = threadIdx.x >> 5;
    if (lane == 0) { as[wid] = s; bs[wid] = ss; }
    __syncthreads();
    if (threadIdx.x == 0) {
        float S = 0.f, SS = 0.f;
        #pragma unroll
        for (int w = 0; w < 8; w++) { S += as[w]; SS += bs[w]; }
        float mean = S * (1.0f / HW);
        float var  = (SS - S * mean) * (1.0f / (HW - 1));
        var = fmaxf(var, 0.0f);
        d_mean[idx] = mean;
        d_inv[idx]  = 1.0f / (sqrtf(var) + 1e-7f);
    }
}

// ---------------------------------------------------------------------------
// Kernel 2: fold 1x1 conv AND instance-norm into 3x3 weights + bias.
// ---------------------------------------------------------------------------
__global__ void combine_kernel(const float* __restrict__ dw,
                               const float* __restrict__ pw,
                               const float* __restrict__ biases) {
    __shared__ float red[72];
    int bo = blockIdx.x;
    int t  = threadIdx.x;          // 0..71
    int o  = bo % O_CH;
    int b  = bo / O_CH;
    int g  = o >> 3;
    int i  = t / 9, tap = t % 9;
    const float* pwp = pw + (size_t)bo * OG;
    float acc = 0.f;
    #pragma unroll
    for (int ip = 0; ip < 8; ip++)
        acc += pwp[ip] * dw[(((size_t)b*O_CH + (g*OG + ip))*CG + i)*9 + tap];
    float inv_i  = d_inv [b*C + g*CG + i];
    float mean_i = d_mean[b*C + g*CG + i];
    float wp = acc * inv_i;
    d_comb[(size_t)bo*72 + t] = wp;
    red[t] = wp * mean_i;
    __syncthreads();
    if (t == 0) {
        float s = 0.f;
        #pragma unroll
        for (int k = 0; k < 72; k++) s += red[k];
        d_bias2[bo] = biases[bo] - s;
    }
}

// ---------------------------------------------------------------------------
// Kernel 3: grouped 3x3 conv via HMMA + ldmatrix, fp16 accumulators
// (two independent chains, combined in fp32 at the epilogue).
// ---------------------------------------------------------------------------
__global__ __launch_bounds__(512, 2) void conv_kernel(const float* __restrict__ x,
                                                      float* __restrict__ out) {
    __shared__ __align__(16) __half tile[TROWS*TC*CG];   // 38016 B
    __shared__ float wsm[OG*72];
    __shared__ float smean[CG];

    int b  = blockIdx.z;
    int g  = blockIdx.y;
    int r0 = blockIdx.x * RSTRIP;
    int tid  = threadIdx.x;
    int lane = tid & 31;
    int wi   = tid >> 5;

    uint32_t sb = smem_u32(tile);

    if (tid < CG) smean[tid] = d_mean[b*C + g*CG + tid];
    {
        const float* cb = d_comb + (size_t)(b*O_CH + g*OG) * 72;
        for (int idx = tid; idx < OG*72; idx += 512) wsm[idx] = cb[idx];
    }
    __syncthreads();

    // ---- staging: task = 8 px x 8 ch -> transpose -> 8 STS.128 ----
    if (tid < NTASK) {
        int row = tid >> 4;
        int w0  = (tid & 15) << 3;
        int grow = r0 - 1 + row;
        uint32_t h[CG][4];
        if ((unsigned)grow < (unsigned)H) {
            const float* xb = x + (size_t)(b*C + g*CG) * HW + (size_t)grow * W + w0;
            #pragma unroll
            for (int ch = 0; ch < CG; ch++) {
                const float4* p = (const float4*)(xb + (size_t)ch * HW);
                float4 A0 = p[0], A1 = p[1];
                h[ch][0] = pkh2(A0.x, A0.y);
                h[ch][1] = pkh2(A0.z, A0.w);
                h[ch][2] = pkh2(A1.x, A1.y);
                h[ch][3] = pkh2(A1.z, A1.w);
            }
        } else {
            #pragma unroll
            for (int ch = 0; ch < CG; ch++) {
                uint32_t mm = pkh2(smean[ch], smean[ch]);
                h[ch][0] = mm; h[ch][1] = mm; h[ch][2] = mm; h[ch][3] = mm;
            }
        }
        #pragma unroll
        for (int p = 0; p < 8; p++) {
            uint32_t sel = (p & 1) ? 0x7632u : 0x5410u;
            int i2 = p >> 1;
            uint32_t q0 = __byte_perm(h[0][i2], h[1][i2], sel);
            uint32_t q1 = __byte_perm(h[2][i2], h[3][i2], sel);
            uint32_t q2 = __byte_perm(h[4][i2], h[5][i2], sel);
            uint32_t q3 = __byte_perm(h[6][i2], h[7][i2], sel);
            uint32_t a16 = (uint32_t)(row*TC + w0 + 1 + p);
            sts128(sb + SW(a16)*16u, q0, q1, q2, q3);
        }
    } else if (tid < NTASK + 36) {
        int idx = tid - NTASK;
        int row = idx >> 1;
        int col = (idx & 1) ? 129 : 0;
        uint32_t q0 = pkh2(smean[0], smean[1]);
        uint32_t q1 = pkh2(smean[2], smean[3]);
        uint32_t q2 = pkh2(smean[4], smean[5]);
        uint32_t q3 = pkh2(smean[6], smean[7]);
        uint32_t a16 = (uint32_t)(row*TC + col);
        sts128(sb + SW(a16)*16u, q0, q1, q2, q3);
    }
    __syncthreads();

    // ---- B fragments (weights), fp16 ----
    int gid = lane >> 2;   // px row within m16 / B col n
    int tg  = lane & 3;    // ch pair selector for D cols
    uint32_t bf[9];
    {
        const float* wn = wsm + gid * 72 + (tg * 2) * 9;
        #pragma unroll
        for (int j = 0; j < 4; j++) {
            bf[2*j + 0] = pkh2(wn[2*j],     wn[9 + 2*j]);
            bf[2*j + 1] = pkh2(wn[2*j + 1], wn[9 + 2*j + 1]);
        }
        bf[8] = pkh2(wn[8], wn[17]);
    }

    // ---- per-thread ldmatrix base offsets ----
    int q  = lane >> 3;
    int l8 = lane & 7;
    int base_j[4], base_8;
    #pragma unroll
    for (int j = 0; j < 4; j++) {
        int t = 2*j + (q >> 1);
        base_j[j] = (wi + t/3)*TC + (q & 1)*8 + l8 + (t % 3);
    }
    base_8 = (wi + 2)*TC + (q & 1)*8 + l8 + 2;

    float bia0 = d_bias2[b*O_CH + g*OG + tg*2];
    float bia1 = d_bias2[b*O_CH + g*OG + tg*2 + 1];

    int hrow = r0 + wi;
    float* obase = out + (size_t)(b*O_CH + g*OG + tg*2) * HW + (size_t)hrow * W;

    #pragma unroll
    for (int ws = 0; ws < 8; ws++) {
        int w16 = ws * 16;
        // two independent fp16 accumulator chains
        uint32_t cA0 = 0u, cA1 = 0u, cB0 = 0u, cB1 = 0u;

        #pragma unroll
        for (int j = 0; j < 4; j++) {
            uint32_t a16 = (uint32_t)(base_j[j] + w16);
            uint32_t addr = sb + SW(a16)*16u;
            uint32_t a0, a1, a2, a3;
            asm volatile("ldmatrix.sync.aligned.m8n8.x4.shared.b16 {%0,%1,%2,%3}, [%4];"
                         : "=r"(a0), "=r"(a1), "=r"(a2), "=r"(a3) : "r"(addr));
            if (j < 2) {
                asm volatile(
                    "mma.sync.aligned.m16n8k16.row.col.f16.f16.f16.f16 "
                    "{%0,%1},{%2,%3,%4,%5},{%6,%7},{%0,%1};"
                    : "+r"(cA0), "+r"(cA1)
                    : "r"(a0), "r"(a1), "r"(a2), "r"(a3),
                      "r"(bf[2*j]), "r"(bf[2*j + 1]));
            } else {
                asm volatile(
                    "mma.sync.aligned.m16n8k16.row.col.f16.f16.f16.f16 "
                    "{%0,%1},{%2,%3,%4,%5},{%6,%7},{%0,%1};"
                    : "+r"(cB0), "+r"(cB1)
                    : "r"(a0), "r"(a1), "r"(a2), "r"(a3),
                      "r"(bf[2*j]), "r"(bf[2*j + 1]));
            }
        }
        {
            uint32_t a16 = (uint32_t)(base_8 + w16);
            uint32_t addr = sb + SW(a16)*16u;
            uint32_t a0, a1;
            asm volatile("ldmatrix.sync.aligned.m8n8.x2.shared.b16 {%0,%1}, [%2];"
                         : "=r"(a0), "=r"(a1) : "r"(addr));
            asm volatile(
                "mma.sync.aligned.m16n8k8.row.col.f16.f16.f16.f16 "
                "{%0,%1},{%2,%3},{%4},{%0,%1};"
                : "+r"(cB0), "+r"(cB1)
                : "r"(a0), "r"(a1), "r"(bf[8]));
        }

        // epilogue: combine chains in fp32, add bias, store
        float2 fa0 = uph2(cA0), fb0 = uph2(cB0);
        float2 fa1 = uph2(cA1), fb1 = uph2(cB1);
        float d0 = fa0.x + fb0.x + bia0;
        float d1 = fa0.y + fb0.y + bia1;
        float d2 = fa1.x + fb1.x + bia0;
        float d3 = fa1.y + fb1.y + bia1;

        float* ob = obase + w16 + gid;
        ob[0]      = d0;
        ob[HW]     = d1;
        ob[8]      = d2;
        ob[HW + 8] = d3;
    }
}

// ---------------------------------------------------------------------------
extern "C" void kernel_launch(void* const* d_in, const int* in_sizes, int n_in,
                              void* d_out, int out_size) {
    const float* x      = (const float*)d_in[0];
    const float* dw     = (const float*)d_in[1];
    const float* pw     = (const float*)d_in[2];
    const float* biases = (const float*)d_in[3];
    float* out = (float*)d_out;

    stats_kernel<<<B*C, 256>>>(x);
    combine_kernel<<<B*O_CH, 72>>>(dw, pw, biases);
    conv_kernel<<<dim3(H/RSTRIP, G, B), 512>>>(x, out);
}